// round 7
// baseline (speedup 1.0000x reference)
#include <cuda_runtime.h>
#include <cuda_bf16.h>
#include <stdint.h>

// ---------------------------------------------------------------------------
// TypeLoss sparsity split (R2 design, coalescing bug fixed):
//   K1 scatter:    atomicOr class bits into per-row uint32 mask (<=200K rows)
//   K2 correction: atomicExch(mask,0) -> unique winner adds
//                  loss(mask) - loss(class0) in int64 fixed point. Self-cleans.
//   K3 main:       PURE logits stream, class-0 closed form, unroll x2 with
//                  coalesced i / i+stride pairs, fused last-block finalize.
// Deterministic: int64 fixed-point correction + fixed-order double reduction.
// ---------------------------------------------------------------------------

#define MAX_PAIRS    9000000         // >= 3000*2999 = 8,997,000
#define MAIN_BLOCKS  1184            // 8 * 148 SMs
#define MAIN_THREADS 256
#define CORR_SCALE   16777216.0f     // 2^24

__device__ unsigned int       g_mask32[MAX_PAIRS];  // zero at load; self-cleaning
__device__ float              g_partials[MAIN_BLOCKS];
__device__ unsigned long long g_corr;
__device__ unsigned int       g_count;

__device__ __forceinline__ int pred_to_type(int pred) {
    if (pred == 1 || (pred >= 14 && pred <= 26)) return 1;
    if (pred >= 2 && pred <= 7)  return 2;
    if (pred >= 8 && pred <= 13) return 3;
    return 0;
}

__device__ __forceinline__ int flat_index(int i, int j, int insnum) {
    return i * (insnum - 1) + j - (i < j ? 1 : 0);
}

// ---- class-0 row loss: -w0*(1-p0)^2*log(p0) ----
__device__ __forceinline__ float row_loss_base(float4 l, float w0) {
    float s = __expf(l.y - l.x) + __expf(l.z - l.x) + __expf(l.w - l.x);
    float t = 1.0f + s;
    float om = __fdividef(s, t);   // 1 - p0
    float lp = __logf(t);          // -log p0
    return w0 * om * om * lp;
}

// ---- K1: scatter class bits (+ reset g_corr) ----
__global__ void scatter_kernel(const int* __restrict__ rel, int n_rel, int insnum) {
    int r = blockIdx.x * blockDim.x + threadIdx.x;
    if (r == 0) g_corr = 0ULL;
    if (r >= n_rel) return;
    int i    = rel[3 * r + 0];
    int j    = rel[3 * r + 1];
    int pred = rel[3 * r + 2];
    if (i == j) return;
    if ((unsigned)i >= (unsigned)insnum || (unsigned)j >= (unsigned)insnum) return;
    int t = pred_to_type(pred < 0 ? 0 : (pred > 63 ? 63 : pred));
    int flat = flat_index(i, j, insnum);
    if ((unsigned)flat >= (unsigned)MAX_PAIRS) return;
    atomicOr(&g_mask32[flat], 1u << t);
}

// ---- K2: correction for touched rows (self-cleaning, deterministic) ----
__global__ void correction_kernel(const float4* __restrict__ logits,
                                  const int* __restrict__ rel, int n_rel,
                                  int insnum,
                                  const float* __restrict__ pred_w) {
    int r = blockIdx.x * blockDim.x + threadIdx.x;
    if (r >= n_rel) return;
    int i = rel[3 * r + 0];
    int j = rel[3 * r + 1];
    if (i == j) return;
    if ((unsigned)i >= (unsigned)insnum || (unsigned)j >= (unsigned)insnum) return;
    int flat = flat_index(i, j, insnum);
    if ((unsigned)flat >= (unsigned)MAX_PAIRS) return;

    unsigned m = atomicExch(&g_mask32[flat], 0u);  // unique winner; resets mask
    if (m == 0u) return;

    float w0 = __ldg(&pred_w[0]), w1 = __ldg(&pred_w[1]);
    float w2 = __ldg(&pred_w[2]), w3 = __ldg(&pred_w[3]);

    float4 l = __ldg(&logits[flat]);
    float e0 = __expf(l.x);
    float e1 = __expf(l.y);
    float e2 = __expf(l.z);
    float e3 = __expf(l.w);
    float S  = (e0 + e1) + (e2 + e3);

    float num = 0.0f, a = 0.0f;
    if (m & 1u) { num += e0; a += w0; }
    if (m & 2u) { num += e1; a += w1; }
    if (m & 4u) { num += e2; a += w2; }
    if (m & 8u) { num += e3; a += w3; }

    float pA  = __fdividef(num, S);
    float omA = 1.0f - pA;
    float lossA = -a * omA * omA * __logf(pA);

    float lossB = row_loss_base(l, w0);

    long long q = llrintf((lossA - lossB) * CORR_SCALE);
    atomicAdd(&g_corr, (unsigned long long)q);
}

// ---- K3: pure logits stream + fused finalize ----
__global__ __launch_bounds__(MAIN_THREADS, 8) void loss_kernel(
    const float4* __restrict__ logits,
    const float*  __restrict__ pred_w,
    int n_pairs,
    float* __restrict__ out)
{
    const float w0 = __ldg(&pred_w[0]);

    float acc = 0.0f;
    const int idx    = blockIdx.x * blockDim.x + threadIdx.x;
    const int stride = gridDim.x * blockDim.x;

    // unroll x2: both loads coalesced (consecutive lanes -> consecutive rows)
    int i = idx;
    for (; i + stride < n_pairs; i += 2 * stride) {
        float4 la = __ldcs(&logits[i]);
        float4 lb = __ldcs(&logits[i + stride]);
        acc += row_loss_base(la, w0);
        acc += row_loss_base(lb, w0);
    }
    if (i < n_pairs)
        acc += row_loss_base(__ldcs(&logits[i]), w0);

    // deterministic block tree reduction
    __shared__ float sdata[MAIN_THREADS];
    sdata[threadIdx.x] = acc;
    __syncthreads();
    #pragma unroll
    for (int s = MAIN_THREADS / 2; s > 0; s >>= 1) {
        if (threadIdx.x < s) sdata[threadIdx.x] += sdata[threadIdx.x + s];
        __syncthreads();
    }

    __shared__ bool is_last;
    if (threadIdx.x == 0) {
        g_partials[blockIdx.x] = sdata[0];
        __threadfence();
        unsigned done = atomicAdd(&g_count, 1u);
        is_last = (done == (unsigned)gridDim.x - 1u);
    }
    __syncthreads();
    if (!is_last) return;

    // last block: fixed-order double reduction + correction, mean, reset
    __threadfence();
    __shared__ double ddata[MAIN_THREADS];
    double dacc = 0.0;
    for (int k = threadIdx.x; k < gridDim.x; k += MAIN_THREADS)
        dacc += (double)g_partials[k];
    ddata[threadIdx.x] = dacc;
    __syncthreads();
    #pragma unroll
    for (int s = MAIN_THREADS / 2; s > 0; s >>= 1) {
        if (threadIdx.x < s) ddata[threadIdx.x] += ddata[threadIdx.x + s];
        __syncthreads();
    }
    if (threadIdx.x == 0) {
        double total = ddata[0] +
            (double)(long long)g_corr * (1.0 / (double)CORR_SCALE);
        out[0] = (float)(total / (double)n_pairs);
        g_count = 0u;
    }
}

// ---------------------------------------------------------------------------
extern "C" void kernel_launch(void* const* d_in, const int* in_sizes, int n_in,
                              void* d_out, int out_size) {
    const float* type_output = (const float*)d_in[0];   // (n_pairs, 4) f32
    const int*   rel_gt      = (const int*)d_in[2];     // (n_rel, 3) int32
    const float* pred_w      = (const float*)d_in[3];   // (4,) f32

    int insnum  = in_sizes[1];
    int n_rel   = in_sizes[2] / 3;
    int n_pairs = insnum * insnum - insnum;

    int rb = (n_rel + 255) / 256;
    scatter_kernel<<<rb, 256>>>(rel_gt, n_rel, insnum);
    correction_kernel<<<rb, 256>>>((const float4*)type_output, rel_gt, n_rel,
                                   insnum, pred_w);
    loss_kernel<<<MAIN_BLOCKS, MAIN_THREADS>>>(
        (const float4*)type_output, pred_w, n_pairs, (float*)d_out);
}

// round 9
// speedup vs baseline: 4.9337x; 4.9337x over previous
#include <cuda_runtime.h>
#include <cuda_bf16.h>
#include <stdint.h>

// ---------------------------------------------------------------------------
// TypeLoss — single fused persistent kernel:
//   bids [0,592):    scatter relations (atomicOr class bits), bump done-ctr
//   bids [592,888):  spin until scatter done, correction via atomicExch
//                    (unique winner, self-cleaning), WARP-reduced int64
//                    fixed-point delta -> 1 atomicAdd per warp (fixes the
//                    ~100us single-address 64-bit atomic serialization)
//   all blocks:      stream logits (class-0 closed form, unroll x4, MLP=4)
//                    over a static skew-weighted partition, block tree
//                    reduction, last-block fixed-order finalize + state reset.
// Fully deterministic: fixed partition, fixed-order sums, integer correction.
// ---------------------------------------------------------------------------

#define MAX_PAIRS   9000000          // >= 3000*2999 = 8,997,000
#define GRID        1184             // 8 * 148 SMs, single wave
#define NTHREADS    256
#define SCAT_B      592              // scatter blocks  [0, 592)
#define CORR_B      296              // correction blks [592, 888)
#define CORR_END    (SCAT_B + CORR_B)
#define W_SCAT      944              // weight/1024: scatter blocks stream less
#define W_CORR      848              // correction blocks stream least
#define W_NORM      1024
#define CORR_SCALE  16777216.0f      // 2^24 fixed point

__device__ unsigned int       g_mask32[MAX_PAIRS];  // zero at load; self-cleaning
__device__ float              g_partials[GRID];
__device__ unsigned long long g_corr;       // zero at load; reset each replay
__device__ unsigned int       g_count;      // arrival counter
__device__ unsigned int       g_scat_done;  // scatter-block done counter

__device__ __forceinline__ int pred_to_type(int pred) {
    if (pred == 1 || (pred >= 14 && pred <= 26)) return 1;
    if (pred >= 2 && pred <= 7)  return 2;
    if (pred >= 8 && pred <= 13) return 3;
    return 0;
}

__device__ __forceinline__ int flat_index(int i, int j, int insnum) {
    return i * (insnum - 1) + j - (i < j ? 1 : 0);
}

// class-0 row loss: -w0*(1-p0)^2*log(p0)
__device__ __forceinline__ float row_loss_base(float4 l, float w0) {
    float s = __expf(l.y - l.x) + __expf(l.z - l.x) + __expf(l.w - l.x);
    float t = 1.0f + s;
    float om = __fdividef(s, t);   // 1 - p0
    float lp = __logf(t);          // -log p0
    return w0 * om * om * lp;
}

// cumulative integer weight of blocks [0, bid)
__device__ __forceinline__ long long cum_weight(int bid) {
    if (bid <= SCAT_B)   return (long long)bid * W_SCAT;
    if (bid <= CORR_END) return (long long)SCAT_B * W_SCAT
                              + (long long)(bid - SCAT_B) * W_CORR;
    return (long long)SCAT_B * W_SCAT + (long long)CORR_B * W_CORR
         + (long long)(bid - CORR_END) * W_NORM;
}

__global__ __launch_bounds__(NTHREADS, 8) void fused_kernel(
    const float4* __restrict__ logits,
    const int*    __restrict__ rel,
    const float*  __restrict__ pred_w,
    int n_rel, int insnum, int n_pairs,
    float* __restrict__ out)
{
    const int bid = blockIdx.x;
    const int tid = threadIdx.x;
    const float w0 = __ldg(&pred_w[0]);

    // ---------------- phase A: roles ----------------
    if (bid < SCAT_B) {
        for (int r = bid * NTHREADS + tid; r < n_rel; r += SCAT_B * NTHREADS) {
            int i    = rel[3 * r + 0];
            int j    = rel[3 * r + 1];
            int pred = rel[3 * r + 2];
            if (i == j) continue;
            if ((unsigned)i >= (unsigned)insnum ||
                (unsigned)j >= (unsigned)insnum) continue;
            int t = pred_to_type(pred < 0 ? 0 : (pred > 63 ? 63 : pred));
            int flat = flat_index(i, j, insnum);
            if ((unsigned)flat >= (unsigned)MAX_PAIRS) continue;
            atomicOr(&g_mask32[flat], 1u << t);
        }
        __threadfence();
        __syncthreads();
        if (tid == 0) atomicAdd(&g_scat_done, 1u);
    } else if (bid < CORR_END) {
        if (tid == 0) {
            volatile unsigned int* p = &g_scat_done;
            while (*p < (unsigned)SCAT_B) __nanosleep(64);
        }
        __syncthreads();
        const float w1 = __ldg(&pred_w[1]);
        const float w2 = __ldg(&pred_w[2]);
        const float w3 = __ldg(&pred_w[3]);

        long long q = 0;
        for (int r = (bid - SCAT_B) * NTHREADS + tid; r < n_rel;
             r += CORR_B * NTHREADS) {
            int i = rel[3 * r + 0];
            int j = rel[3 * r + 1];
            if (i == j) continue;
            if ((unsigned)i >= (unsigned)insnum ||
                (unsigned)j >= (unsigned)insnum) continue;
            int flat = flat_index(i, j, insnum);
            if ((unsigned)flat >= (unsigned)MAX_PAIRS) continue;

            unsigned m = atomicExch(&g_mask32[flat], 0u); // winner; self-clean
            if (m == 0u) continue;

            float4 l = __ldg(&logits[flat]);
            float e0 = __expf(l.x);
            float e1 = __expf(l.y);
            float e2 = __expf(l.z);
            float e3 = __expf(l.w);
            float S  = (e0 + e1) + (e2 + e3);

            float num = 0.0f, a = 0.0f;
            if (m & 1u) { num += e0; a += w0; }
            if (m & 2u) { num += e1; a += w1; }
            if (m & 4u) { num += e2; a += w2; }
            if (m & 8u) { num += e3; a += w3; }

            float pA  = __fdividef(num, S);
            float omA = 1.0f - pA;
            float lossA = -a * omA * omA * __logf(pA);
            float lossB = row_loss_base(l, w0);
            q += (long long)llrintf((lossA - lossB) * CORR_SCALE);
        }
        // warp-reduce the int64 delta -> one atomic per warp
        #pragma unroll
        for (int off = 16; off > 0; off >>= 1)
            q += __shfl_xor_sync(0xffffffffu, q, off);
        if ((tid & 31) == 0 && q != 0)
            atomicAdd(&g_corr, (unsigned long long)q);
    }

    // ---------------- phase B: logits stream ----------------
    const long long TW = cum_weight(GRID);
    int s  = (int)(((long long)n_pairs * cum_weight(bid)) / TW);
    int re = (int)(((long long)n_pairs * cum_weight(bid + 1)) / TW);

    float acc = 0.0f;
    int r = s + tid;
    for (; r + 3 * NTHREADS < re; r += 4 * NTHREADS) {
        float4 a = __ldcs(&logits[r]);
        float4 b = __ldcs(&logits[r +     NTHREADS]);
        float4 c = __ldcs(&logits[r + 2 * NTHREADS]);
        float4 d = __ldcs(&logits[r + 3 * NTHREADS]);
        acc += row_loss_base(a, w0);
        acc += row_loss_base(b, w0);
        acc += row_loss_base(c, w0);
        acc += row_loss_base(d, w0);
    }
    for (; r < re; r += NTHREADS)
        acc += row_loss_base(__ldcs(&logits[r]), w0);

    // deterministic block tree reduction
    __shared__ float sdata[NTHREADS];
    sdata[tid] = acc;
    __syncthreads();
    #pragma unroll
    for (int st = NTHREADS / 2; st > 0; st >>= 1) {
        if (tid < st) sdata[tid] += sdata[tid + st];
        __syncthreads();
    }

    __shared__ bool is_last;
    if (tid == 0) {
        g_partials[bid] = sdata[0];
        __threadfence();
        unsigned done = atomicAdd(&g_count, 1u);
        is_last = (done == (unsigned)GRID - 1u);
    }
    __syncthreads();
    if (!is_last) return;

    // ---------------- phase C: last-block finalize ----------------
    __threadfence();
    __shared__ double ddata[NTHREADS];
    double dacc = 0.0;
    for (int k = tid; k < GRID; k += NTHREADS)
        dacc += (double)g_partials[k];
    ddata[tid] = dacc;
    __syncthreads();
    #pragma unroll
    for (int st = NTHREADS / 2; st > 0; st >>= 1) {
        if (tid < st) ddata[tid] += ddata[tid + st];
        __syncthreads();
    }
    if (tid == 0) {
        double total = ddata[0] +
            (double)(long long)g_corr * (1.0 / (double)CORR_SCALE);
        out[0] = (float)(total / (double)n_pairs);
        g_count     = 0u;   // reset state for next graph replay
        g_scat_done = 0u;
        g_corr      = 0ULL;
    }
}

// ---------------------------------------------------------------------------
extern "C" void kernel_launch(void* const* d_in, const int* in_sizes, int n_in,
                              void* d_out, int out_size) {
    const float* type_output = (const float*)d_in[0];   // (n_pairs, 4) f32
    const int*   rel_gt      = (const int*)d_in[2];     // (n_rel, 3) int32
    const float* pred_w      = (const float*)d_in[3];   // (4,) f32

    int insnum  = in_sizes[1];
    int n_rel   = in_sizes[2] / 3;
    int n_pairs = insnum * insnum - insnum;

    fused_kernel<<<GRID, NTHREADS>>>(
        (const float4*)type_output, rel_gt, pred_w,
        n_rel, insnum, n_pairs, (float*)d_out);
}